// round 3
// baseline (speedup 1.0000x reference)
#include <cuda_runtime.h>

#define D        128
#define MAX_OUT  100000

// Scratch (allocation-free rule: __device__ globals)
__device__ float g_S[(size_t)MAX_OUT * D];      // segment sums, 51.2 MB
__device__ int   g_row_start[MAX_OUT + 1];      // CSR-style segment offsets

// ---------------------------------------------------------------------------
// Kernel 0: init row_start[s] = E for all s (covers trailing empty segments
// and the row_start[n_out] sentinel).
// ---------------------------------------------------------------------------
__global__ void init_row_start(int n_out, int E) {
    int i = blockIdx.x * blockDim.x + threadIdx.x;
    if (i <= n_out) g_row_start[i] = E;
}

// ---------------------------------------------------------------------------
// Kernel 1: segment_ids is sorted (int32); each edge marks its
// first-occurrence boundary. Empty segments between consecutive distinct ids
// get the same start as the following non-empty one (so end-start == 0).
// ---------------------------------------------------------------------------
__global__ void mark_boundaries(const int* __restrict__ seg, int E) {
    int e = blockIdx.x * blockDim.x + threadIdx.x;
    if (e >= E) return;
    int s  = seg[e];
    int sp = (e == 0) ? -1 : seg[e - 1];
    for (int t = sp + 1; t <= s; ++t) g_row_start[t] = e;
}

// ---------------------------------------------------------------------------
// Kernel 2: one warp per output segment. Lane l owns float4 D-slice [4l,4l+4).
// Per edge: broadcast idx load + 32 coalesced 16B accesses (4 x 128B lines).
// 2-edge unroll with independent accumulators for MLP.
// ---------------------------------------------------------------------------
__global__ __launch_bounds__(256) void seg_gather_sum(
    const float* __restrict__ values,
    const int* __restrict__ gidx,
    int n_out)
{
    int warp = (blockIdx.x * blockDim.x + threadIdx.x) >> 5;
    if (warp >= n_out) return;
    int lane = threadIdx.x & 31;
    int c = lane * 4;

    int e0 = g_row_start[warp];
    int e1 = g_row_start[warp + 1];

    float4 a0 = make_float4(0.f, 0.f, 0.f, 0.f);
    float4 a1 = make_float4(0.f, 0.f, 0.f, 0.f);

    int e = e0;
    for (; e + 2 <= e1; e += 2) {
        long long i0 = (long long)__ldg(gidx + e);
        long long i1 = (long long)__ldg(gidx + e + 1);
        float4 v0 = __ldg(reinterpret_cast<const float4*>(values + i0 * D + c));
        float4 v1 = __ldg(reinterpret_cast<const float4*>(values + i1 * D + c));
        a0.x += v0.x; a0.y += v0.y; a0.z += v0.z; a0.w += v0.w;
        a1.x += v1.x; a1.y += v1.y; a1.z += v1.z; a1.w += v1.w;
    }
    if (e < e1) {
        long long i0 = (long long)__ldg(gidx + e);
        float4 v0 = __ldg(reinterpret_cast<const float4*>(values + i0 * D + c));
        a0.x += v0.x; a0.y += v0.y; a0.z += v0.z; a0.w += v0.w;
    }

    float4 acc;
    acc.x = a0.x + a1.x; acc.y = a0.y + a1.y;
    acc.z = a0.z + a1.z; acc.w = a0.w + a1.w;
    *reinterpret_cast<float4*>(g_S + (size_t)warp * D + c) = acc;
}

// ---------------------------------------------------------------------------
// Kernel 3: out = tanh(S @ W).  S: [M,128], W: [128,128] row-major.
// BM=128 rows/block, full N=128, BK=8, 256 threads, 8x8 register tile.
// ---------------------------------------------------------------------------
#define BM 128
#define BK 8

__global__ __launch_bounds__(256) void gemm_tanh(
    const float* __restrict__ Wmat,
    float* __restrict__ out,
    int M)
{
    __shared__ float As[BK][BM];   // transposed A tile
    __shared__ float Bs[BK][D];

    int block_row = blockIdx.x * BM;
    int tid = threadIdx.x;
    int tx = tid & 15;             // 16 cols of 8
    int ty = tid >> 4;             // 16 rows of 8

    float acc[8][8];
    #pragma unroll
    for (int i = 0; i < 8; ++i)
        #pragma unroll
        for (int j = 0; j < 8; ++j) acc[i][j] = 0.f;

    const float* A = g_S;

    // A-load mapping: 128 rows x 8 cols = 1024 floats = 256 threads * float4
    int ar  = tid >> 1;            // 0..127
    int akc = (tid & 1) * 4;       // 0 or 4
    // B-load mapping: 8 rows x 128 cols
    int br = tid >> 5;             // 0..7
    int bc = (tid & 31) * 4;

    for (int k0 = 0; k0 < D; k0 += BK) {
        int grow = block_row + ar;
        float4 av = (grow < M)
            ? *reinterpret_cast<const float4*>(A + (size_t)grow * D + k0 + akc)
            : make_float4(0.f, 0.f, 0.f, 0.f);
        As[akc + 0][ar] = av.x;
        As[akc + 1][ar] = av.y;
        As[akc + 2][ar] = av.z;
        As[akc + 3][ar] = av.w;

        *reinterpret_cast<float4*>(&Bs[br][bc]) =
            *reinterpret_cast<const float4*>(Wmat + (size_t)(k0 + br) * D + bc);

        __syncthreads();

        #pragma unroll
        for (int k = 0; k < BK; ++k) {
            float4 ra0 = *reinterpret_cast<const float4*>(&As[k][ty * 8]);
            float4 ra1 = *reinterpret_cast<const float4*>(&As[k][ty * 8 + 4]);
            float4 rb0 = *reinterpret_cast<const float4*>(&Bs[k][tx * 8]);
            float4 rb1 = *reinterpret_cast<const float4*>(&Bs[k][tx * 8 + 4]);
            float ra[8] = {ra0.x, ra0.y, ra0.z, ra0.w, ra1.x, ra1.y, ra1.z, ra1.w};
            float rb[8] = {rb0.x, rb0.y, rb0.z, rb0.w, rb1.x, rb1.y, rb1.z, rb1.w};
            #pragma unroll
            for (int i = 0; i < 8; ++i)
                #pragma unroll
                for (int j = 0; j < 8; ++j)
                    acc[i][j] += ra[i] * rb[j];
        }
        __syncthreads();
    }

    #pragma unroll
    for (int i = 0; i < 8; ++i) {
        int r = block_row + ty * 8 + i;
        if (r < M) {
            #pragma unroll
            for (int j = 0; j < 8; j += 4) {
                float4 o;
                o.x = tanhf(acc[i][j + 0]);
                o.y = tanhf(acc[i][j + 1]);
                o.z = tanhf(acc[i][j + 2]);
                o.w = tanhf(acc[i][j + 3]);
                *reinterpret_cast<float4*>(out + (size_t)r * D + tx * 8 + j) = o;
            }
        }
    }
}

// ---------------------------------------------------------------------------
// Launch
// ---------------------------------------------------------------------------
extern "C" void kernel_launch(void* const* d_in, const int* in_sizes, int n_in,
                              void* d_out, int out_size)
{
    const float* values = (const float*)d_in[0];   // [N_SRC, 128] f32
    const float* Wmat   = (const float*)d_in[1];   // [128, 128] f32
    const int*   gidx   = (const int*)d_in[2];     // [E] int32 (JAX x64 disabled)
    const int*   seg    = (const int*)d_in[3];     // [E] int32, sorted

    int E     = in_sizes[2];
    int n_out = out_size / D;
    float* out = (float*)d_out;

    init_row_start<<<(n_out + 256) / 256, 256>>>(n_out, E);
    mark_boundaries<<<(E + 255) / 256, 256>>>(seg, E);
    seg_gather_sum<<<(n_out * 32 + 255) / 256, 256>>>(values, gidx, n_out);
    gemm_tanh<<<(n_out + BM - 1) / BM, 256>>>(Wmat, out, n_out);
}

// round 6
// speedup vs baseline: 1.4322x; 1.4322x over previous
#include <cuda_runtime.h>
#include <cstdint>

#define D        128
#define MAX_OUT  100000
#define M_PAD    100352   // 784*128: tile-overrun padding for g_S reads

// Scratch (allocation-free rule: __device__ globals; zero-initialized)
__device__ float g_S[(size_t)M_PAD * D];   // segment sums (pad rows stay zero)
__device__ float g_Wt[D * D];              // W transposed: Wt[n][k] = W[k][n]
__device__ int   g_row_start[MAX_OUT + 1];

// ---------------------------------------------------------------------------
// helpers
// ---------------------------------------------------------------------------
static __device__ __forceinline__ uint32_t f2tf32(float f) {
    uint32_t r;
    asm("cvt.rna.tf32.f32 %0, %1;" : "=r"(r) : "f"(f));
    return r;
}
static __device__ __forceinline__ void mma_tf32(
    float& c0, float& c1, float& c2, float& c3,
    uint32_t a0, uint32_t a1, uint32_t a2, uint32_t a3,
    uint32_t b0, uint32_t b1)
{
    asm volatile(
        "mma.sync.aligned.m16n8k8.row.col.f32.tf32.tf32.f32 "
        "{%0,%1,%2,%3}, {%4,%5,%6,%7}, {%8,%9}, {%0,%1,%2,%3};"
        : "+f"(c0), "+f"(c1), "+f"(c2), "+f"(c3)
        : "r"(a0), "r"(a1), "r"(a2), "r"(a3), "r"(b0), "r"(b1));
}

// ---------------------------------------------------------------------------
// transpose W (128x128) into g_Wt.  grid=16 (4x4 tiles), block=(32,8)
// ---------------------------------------------------------------------------
__global__ void transpose_W(const float* __restrict__ W) {
    __shared__ float t[32][33];
    int bx = blockIdx.x & 3, by = blockIdx.x >> 2;
    int x = bx * 32 + threadIdx.x;
    #pragma unroll
    for (int i = 0; i < 4; ++i) {
        int y = by * 32 + threadIdx.y * 4 + i;
        t[threadIdx.y * 4 + i][threadIdx.x] = W[y * D + x];
    }
    __syncthreads();
    #pragma unroll
    for (int i = 0; i < 4; ++i) {
        int n = bx * 32 + threadIdx.y * 4 + i;
        g_Wt[n * D + by * 32 + threadIdx.x] = t[threadIdx.x][threadIdx.y * 4 + i];
    }
}

// ---------------------------------------------------------------------------
// segment CSR construction
// ---------------------------------------------------------------------------
__global__ void init_row_start(int n_out, int E) {
    int i = blockIdx.x * blockDim.x + threadIdx.x;
    if (i <= n_out) g_row_start[i] = E;
}
__global__ void mark_boundaries(const int* __restrict__ seg, int E) {
    int e = blockIdx.x * blockDim.x + threadIdx.x;
    if (e >= E) return;
    int s  = seg[e];
    int sp = (e == 0) ? -1 : seg[e - 1];
    for (int t = sp + 1; t <= s; ++t) g_row_start[t] = e;
}

// ---------------------------------------------------------------------------
// warp-per-segment gather-sum (unchanged — near L2 floor)
// ---------------------------------------------------------------------------
__global__ __launch_bounds__(256) void seg_gather_sum(
    const float* __restrict__ values,
    const int* __restrict__ gidx,
    int n_out)
{
    int warp = (blockIdx.x * blockDim.x + threadIdx.x) >> 5;
    if (warp >= n_out) return;
    int lane = threadIdx.x & 31;
    int c = lane * 4;

    int e0 = g_row_start[warp];
    int e1 = g_row_start[warp + 1];

    float4 a0 = make_float4(0.f, 0.f, 0.f, 0.f);
    float4 a1 = make_float4(0.f, 0.f, 0.f, 0.f);

    int e = e0;
    for (; e + 2 <= e1; e += 2) {
        long long i0 = (long long)__ldg(gidx + e);
        long long i1 = (long long)__ldg(gidx + e + 1);
        float4 v0 = __ldg(reinterpret_cast<const float4*>(values + i0 * D + c));
        float4 v1 = __ldg(reinterpret_cast<const float4*>(values + i1 * D + c));
        a0.x += v0.x; a0.y += v0.y; a0.z += v0.z; a0.w += v0.w;
        a1.x += v1.x; a1.y += v1.y; a1.z += v1.z; a1.w += v1.w;
    }
    if (e < e1) {
        long long i0 = (long long)__ldg(gidx + e);
        float4 v0 = __ldg(reinterpret_cast<const float4*>(values + i0 * D + c));
        a0.x += v0.x; a0.y += v0.y; a0.z += v0.z; a0.w += v0.w;
    }

    float4 acc;
    acc.x = a0.x + a1.x; acc.y = a0.y + a1.y;
    acc.z = a0.z + a1.z; acc.w = a0.w + a1.w;
    *reinterpret_cast<float4*>(g_S + (size_t)warp * D + c) = acc;
}

// ---------------------------------------------------------------------------
// tf32 mma.sync GEMM + tanh.  out = tanh(S @ W) with B = Wt[n][k].
// CTA: 128(M) x 128(N), K chunked by 64. 8 warps: (wid&3)->m32, (wid>>2)->n64.
// Smem padded [128][68]: fragment loads are bank-conflict-free (4*row+k).
// ---------------------------------------------------------------------------
#define BK      64
#define LDS_PAD 68                       // 64 + 4 floats
#define AS_FLOATS (128 * LDS_PAD)
#define SMEM_FLOATS (2 * AS_FLOATS)      // As + Bs

__global__ __launch_bounds__(256, 2) void gemm_tanh_mma(
    float* __restrict__ out, int M)
{
    extern __shared__ float smem[];
    float* As = smem;                    // [128][68] tf32 bits (as float storage)
    float* Bs = smem + AS_FLOATS;        // [128][68]

    int tid  = threadIdx.x;
    int wid  = tid >> 5;
    int lane = tid & 31;
    int wr   = (wid & 3) * 32;           // warp m offset
    int wc   = (wid >> 2) * 64;          // warp n offset
    int gq   = lane >> 2;                // groupID 0..7
    int tg   = lane & 3;                 // thread-in-group 0..3

    int block_row = blockIdx.x * 128;

    float acc[2][8][4];
    #pragma unroll
    for (int mt = 0; mt < 2; ++mt)
        #pragma unroll
        for (int nt = 0; nt < 8; ++nt)
            #pragma unroll
            for (int q = 0; q < 4; ++q) acc[mt][nt][q] = 0.f;

    for (int kc = 0; kc < 2; ++kc) {
        // ---- stage A and B k-chunk, converting to tf32 ----
        // 128 rows x 16 float4 per array; 256 threads x 8 float4 each.
        __syncthreads();
        #pragma unroll
        for (int i = 0; i < 8; ++i) {
            int f   = i * 256 + tid;     // 0..2047
            int row = f >> 4;
            int kq  = f & 15;
            float4 va = __ldg(reinterpret_cast<const float4*>(
                g_S + (size_t)(block_row + row) * D + kc * BK + kq * 4));
            uint4 ta = make_uint4(f2tf32(va.x), f2tf32(va.y), f2tf32(va.z), f2tf32(va.w));
            *reinterpret_cast<uint4*>(As + row * LDS_PAD + kq * 4) = ta;

            float4 vb = __ldg(reinterpret_cast<const float4*>(
                g_Wt + (size_t)row * D + kc * BK + kq * 4));
            uint4 tb = make_uint4(f2tf32(vb.x), f2tf32(vb.y), f2tf32(vb.z), f2tf32(vb.w));
            *reinterpret_cast<uint4*>(Bs + row * LDS_PAD + kq * 4) = tb;
        }
        __syncthreads();

        // ---- 8 k-steps of k=8 ----
        #pragma unroll
        for (int ks = 0; ks < 8; ++ks) {
            int k0 = ks * 8;
            uint32_t a[2][4];
            #pragma unroll
            for (int mt = 0; mt < 2; ++mt) {
                const uint32_t* ap = reinterpret_cast<const uint32_t*>(
                    As + (wr + mt * 16 + gq) * LDS_PAD + k0 + tg);
                a[mt][0] = ap[0];
                a[mt][2] = ap[4];
                const uint32_t* ap8 = reinterpret_cast<const uint32_t*>(
                    As + (wr + mt * 16 + gq + 8) * LDS_PAD + k0 + tg);
                a[mt][1] = ap8[0];
                a[mt][3] = ap8[4];
            }
            uint32_t b[8][2];
            #pragma unroll
            for (int nt = 0; nt < 8; ++nt) {
                const uint32_t* bp = reinterpret_cast<const uint32_t*>(
                    Bs + (wc + nt * 8 + gq) * LDS_PAD + k0 + tg);
                b[nt][0] = bp[0];
                b[nt][1] = bp[4];
            }
            #pragma unroll
            for (int mt = 0; mt < 2; ++mt)
                #pragma unroll
                for (int nt = 0; nt < 8; ++nt)
                    mma_tf32(acc[mt][nt][0], acc[mt][nt][1],
                             acc[mt][nt][2], acc[mt][nt][3],
                             a[mt][0], a[mt][1], a[mt][2], a[mt][3],
                             b[nt][0], b[nt][1]);
        }
    }

    // ---- epilogue: tanh + float2 stores ----
    #pragma unroll
    for (int mt = 0; mt < 2; ++mt) {
        int r0 = block_row + wr + mt * 16 + gq;
        int r1 = r0 + 8;
        #pragma unroll
        for (int nt = 0; nt < 8; ++nt) {
            int col = wc + nt * 8 + tg * 2;
            if (r0 < M) {
                float2 o0;
                o0.x = tanhf(acc[mt][nt][0]);
                o0.y = tanhf(acc[mt][nt][1]);
                *reinterpret_cast<float2*>(out + (size_t)r0 * D + col) = o0;
            }
            if (r1 < M) {
                float2 o1;
                o1.x = tanhf(acc[mt][nt][2]);
                o1.y = tanhf(acc[mt][nt][3]);
                *reinterpret_cast<float2*>(out + (size_t)r1 * D + col) = o1;
            }
        }
    }
}

// ---------------------------------------------------------------------------
// Launch
// ---------------------------------------------------------------------------
extern "C" void kernel_launch(void* const* d_in, const int* in_sizes, int n_in,
                              void* d_out, int out_size)
{
    const float* values = (const float*)d_in[0];   // [N_SRC, 128] f32
    const float* Wmat   = (const float*)d_in[1];   // [128, 128] f32
    const int*   gidx   = (const int*)d_in[2];     // [E] int32
    const int*   seg    = (const int*)d_in[3];     // [E] int32, sorted

    int E     = in_sizes[2];
    int n_out = out_size / D;
    float* out = (float*)d_out;

    static int smem_set = 0;
    if (!smem_set) {
        cudaFuncSetAttribute(gemm_tanh_mma,
                             cudaFuncAttributeMaxDynamicSharedMemorySize,
                             SMEM_FLOATS * (int)sizeof(float));
        smem_set = 1;
    }

    transpose_W<<<16, dim3(32, 8)>>>(Wmat);
    init_row_start<<<(n_out + 256) / 256, 256>>>(n_out, E);
    mark_boundaries<<<(E + 255) / 256, 256>>>(seg, E);
    seg_gather_sum<<<(n_out * 32 + 255) / 256, 256>>>(values, gidx, n_out);
    gemm_tanh_mma<<<(n_out + 127) / 128, 256, SMEM_FLOATS * sizeof(float)>>>(out, n_out);
}